// round 17
// baseline (speedup 1.0000x reference)
#include <cuda_runtime.h>
#include <math.h>
#include <stdint.h>

// Problem constants
#define B 8
#define A 100000
#define M 32
#define C 80
#define APB 320                      // threads; anchors per tile (16*20)
#define NTILES ((A + APB - 1) / APB) // 313
#define NBLK (NTILES * B)            // 2504 sweep tiles
#define NASSIGN NTILES               // 313 assign CTAs (1 anchor range x 8 images)
#define GRID (NASSIGN + NBLK)        // 2817
#define V4PA (C / 4)                 // float4 per anchor = 20
#define NFLAT (APB * V4PA)           // 6400 sums per tile
#define SPAD(i) ((i) + ((i) >> 5))   // shared pad to soften gather conflicts
#define SMEM_DYN ((NFLAT + NFLAT / 32) * 4)   // 26.4KB dynamic (s_flat)

// mask weight for contributing anchors: -0.75 * ln(2)
#define NEGW (-0.5198603854199589f)

// Device-global scratch (no allocation allowed)
__device__ float    g_mask[NBLK * APB];  // per-anchor mask (3.2MB)
__device__ float    g_corr[NBLK];        // per-tile positive-class corrections
__device__ float    g_regp[NBLK];        // per-tile regression partials
__device__ int      g_posp[NBLK];        // per-tile positive counts
__device__ float    g_clsp[NBLK];        // per-tile sweep partials
__device__ unsigned g_flag[NBLK];        // tile-ready flags (reset by finalize)
__device__ unsigned g_ticket = 0;

__device__ __forceinline__ unsigned ld_acquire_gpu(const unsigned* p) {
    unsigned v;
    asm volatile("ld.global.acquire.gpu.u32 %0, [%1];" : "=r"(v) : "l"(p) : "memory");
    return v;
}

__global__ __launch_bounds__(APB, 5) void fl_ws2_kernel(
    const float* __restrict__ cls,      // [B, A, C]
    const float* __restrict__ reg,      // [B, A, 4]
    const float* __restrict__ anchors,  // [1, A, 4]
    const float* __restrict__ ann,      // [B, M, 6]
    float* __restrict__ out)            // [2]
{
    extern __shared__ __align__(16) float s_flat[];   // unmasked sums (sweep)

    __shared__ float4 s_box8[B][M];      // assign role
    __shared__ float2 s_misc8[B][M];
    __shared__ float  s_mask[APB];       // sweep role
    __shared__ float  s_rc[APB / 32];
    __shared__ float  s_rr[APB / 32];
    __shared__ int    s_rp[APB / 32];
    __shared__ bool   s_last;

    const int tid  = threadIdx.x;
    const int wid  = tid >> 5;
    const int lane = tid & 31;
    const int bid  = blockIdx.x;

    if (bid < NASSIGN) {
        // ===================== ASSIGN role (wave-1 resident, pure ALU) =====
        const int r  = bid;
        const int a0 = r * APB;
        const int a  = a0 + tid;
        const bool va = (a < A);

        if (tid < B * M) {
            const int img = tid >> 5;
            const int j   = tid & 31;
            const float* ap = ann + (img * M + j) * 6;
            float x1 = ap[0], y1 = ap[1], x2 = ap[2], y2 = ap[3];
            const float cl = ap[4];
            float area = (x2 - x1) * (y2 - y1);
            if (cl == -1.0f) {
                // Invalid GT: far-away box -> inter == 0 always, area 0 ->
                // identical classification/argmax behavior to iou = -1.
                x1 = 3e9f; y1 = 3e9f; x2 = 3e9f; y2 = 3e9f; area = 0.0f;
            }
            s_box8[img][j]  = make_float4(x1, y1, x2, y2);
            s_misc8[img][j] = make_float2(area, cl);
        }
        __syncthreads();

        float ax1 = 0.f, ay1 = 0.f, ax2 = 0.f, ay2 = 0.f;
        float aw = 1.f, ah = 1.f, area_a = 1.f, acx = 0.f, acy = 0.f;
        if (va) {
            const float4 av = *reinterpret_cast<const float4*>(anchors + a * 4);
            ax1 = av.x; ay1 = av.y; ax2 = av.z; ay2 = av.w;
            aw = ax2 - ax1; ah = ay2 - ay1;
            area_a = aw * ah;
            acx = ax1 + 0.5f * aw;
            acy = ay1 + 0.5f * ah;
        }

        for (int p = 0; p < B; p++) {
            const int t = p * NTILES + r;
            __syncthreads();   // s_rc/s_rr/s_rp reuse

            float mask_val = 0.0f;
            float corr = 0.0f, regl = 0.0f;
            int   posc = 0;

            if (va) {
                float b_in = -1.0f, b_ua = 1.0f;
                int   bi = 0;
                #pragma unroll 8
                for (int j = 0; j < M; j++) {
                    const float4 g  = s_box8[p][j];
                    const float2 mi = s_misc8[p][j];
                    const float iw = fminf(ax2, g.z) - fmaxf(ax1, g.x);
                    const float ih = fminf(ay2, g.w) - fmaxf(ay1, g.y);
                    const float inter = fmaxf(iw, 0.0f) * fmaxf(ih, 0.0f);
                    const float ua = (area_a + mi.x) - inter;
                    if (inter * b_ua > b_in * ua) { b_in = inter; b_ua = ua; bi = j; }
                }
                const bool pos = (b_in >= 0.5f * b_ua);
                const bool ign = (!pos) && (b_in >= 0.4f * b_ua);
                mask_val = ign ? 0.0f : NEGW;

                if (pos) {
                    posc = 1;
                    const float4 g = s_box8[p][bi];
                    const int cid = (int)s_misc8[p][bi].y;
                    const float p_raw = cls[((size_t)p * A + a) * C + cid];
                    const float sweep_term =
                        NEGW * (p_raw * p_raw * __log2f(1.0f - p_raw));
                    const float pc = fminf(fmaxf(p_raw, 1e-4f), 1.0f - 1e-4f);
                    const float qc = 1.0f - pc;
                    corr = 0.25f * qc * qc * (-__logf(pc)) - sweep_term;

                    float gw = g.z - g.x;
                    float gh = g.w - g.y;
                    const float gcx = g.x + 0.5f * gw;
                    const float gcy = g.y + 0.5f * gh;
                    gw = fmaxf(gw, 1.0f);
                    gh = fmaxf(gh, 1.0f);
                    const float t0 = ((gcx - acx) / aw) * 10.0f;
                    const float t1 = ((gcy - acy) / ah) * 10.0f;
                    const float t2 = __logf(gw / aw) * 5.0f;
                    const float t3 = __logf(gh / ah) * 5.0f;
                    const float4 rv4 = *reinterpret_cast<const float4*>(
                        reg + ((size_t)p * A + a) * 4);
                    const float d0 = fabsf(t0 - rv4.x);
                    const float d1 = fabsf(t1 - rv4.y);
                    const float d2 = fabsf(t2 - rv4.z);
                    const float d3 = fabsf(t3 - rv4.w);
                    const float th = 1.0f / 9.0f;
                    const float c2 = 0.5f / 9.0f;
                    regl  = (d0 <= th) ? 4.5f * d0 * d0 : d0 - c2;
                    regl += (d1 <= th) ? 4.5f * d1 * d1 : d1 - c2;
                    regl += (d2 <= th) ? 4.5f * d2 * d2 : d2 - c2;
                    regl += (d3 <= th) ? 4.5f * d3 * d3 : d3 - c2;
                }
            }
            g_mask[(size_t)t * APB + tid] = mask_val;

            float cv = corr, rv = regl;
            int pv = posc;
            #pragma unroll
            for (int o = 16; o > 0; o >>= 1) {
                cv += __shfl_down_sync(0xFFFFFFFFu, cv, o);
                rv += __shfl_down_sync(0xFFFFFFFFu, rv, o);
                pv += __shfl_down_sync(0xFFFFFFFFu, pv, o);
            }
            if (lane == 0) { s_rc[wid] = cv; s_rr[wid] = rv; s_rp[wid] = pv; }
            __syncthreads();
            if (tid == 0) {
                float c = 0.0f, rr = 0.0f;
                int pp = 0;
                #pragma unroll
                for (int i = 0; i < APB / 32; i++) {
                    c += s_rc[i]; rr += s_rr[i]; pp += s_rp[i];
                }
                g_corr[t] = c;
                g_regp[t] = rr;
                g_posp[t] = pp;
                __threadfence();                 // publish mask + partials
                atomicExch(&g_flag[t], 1u);      // release tile t
            }
        }
        return;
    }

    // ===================== SWEEP role ======================================
    // ALL memory work happens immediately (no dependency on assign); the
    // flag wait is deferred to AFTER the streaming compute, where it costs
    // ~nothing because assign CTAs (wave-1 ALU-bound) finished long ago.
    const int t   = bid - NASSIGN;
    const int b   = t / NTILES;
    const int tx  = t - b * NTILES;
    const int a0  = tx * APB;
    const int nA  = min(APB, A - a0);
    const int n4  = nA * V4PA;

    const float4* __restrict__ cp4 =
        reinterpret_cast<const float4*>(cls + ((size_t)b * A + a0) * C);

    // s = sum_i p_i^2 * log2(1 - p_i) -> s_flat (unmasked)
    #define NT4W(v, k)                                                       \
    {                                                                        \
        const float l0 = __log2f(1.0f - (v).x);                              \
        const float l1 = __log2f(1.0f - (v).y);                              \
        const float l2 = __log2f(1.0f - (v).z);                              \
        const float l3 = __log2f(1.0f - (v).w);                              \
        const float q0 = (v).x * (v).x;                                      \
        const float q1 = (v).y * (v).y;                                      \
        const float q2 = (v).z * (v).z;                                      \
        const float q3 = (v).w * (v).w;                                      \
        s_flat[SPAD((k) * APB + tid)] =                                      \
            fmaf(q0, l0, fmaf(q1, l1, fmaf(q2, l2, q3 * l3)));               \
    }

    if (nA == APB) {
        #define FL_GROUP(gbase)                                              \
        {                                                                    \
            const float4 v0 = __ldcs(cp4 + (tid + (gbase + 0) * APB));       \
            const float4 v1 = __ldcs(cp4 + (tid + (gbase + 1) * APB));       \
            const float4 v2 = __ldcs(cp4 + (tid + (gbase + 2) * APB));       \
            const float4 v3 = __ldcs(cp4 + (tid + (gbase + 3) * APB));       \
            const float4 v4 = __ldcs(cp4 + (tid + (gbase + 4) * APB));       \
            NT4W(v0, (gbase + 0)) NT4W(v1, (gbase + 1)) NT4W(v2, (gbase + 2))\
            NT4W(v3, (gbase + 3)) NT4W(v4, (gbase + 4))                      \
        }
        FL_GROUP(0)
        FL_GROUP(5)
        FL_GROUP(10)
        FL_GROUP(15)
        #undef FL_GROUP
    } else {
        for (int k = 0; k < V4PA; k++) {
            const int i4 = tid + k * APB;
            if (i4 < n4) {
                const float4 v = __ldcs(cp4 + i4);
                NT4W(v, k)
            } else {
                s_flat[SPAD(k * APB + tid)] = 0.0f;
            }
        }
    }
    #undef NT4W

    // NOW wait for this tile's masks (assign long finished in steady state)
    if (tid == 0) {
        while (ld_acquire_gpu(&g_flag[t]) == 0u) { __nanosleep(100); }
    }
    __syncthreads();   // s_flat writes + flag both visible
    s_mask[tid] = g_mask[(size_t)t * APB + tid];
    __syncthreads();

    // combine: thread tid owns anchor tid -> gathers its 20 unmasked sums
    float S = 0.0f;
    #pragma unroll
    for (int j = 0; j < V4PA; j++)
        S += s_flat[SPAD(V4PA * tid + j)];
    float cv = s_mask[tid] * S;

    #pragma unroll
    for (int o = 16; o > 0; o >>= 1)
        cv += __shfl_down_sync(0xFFFFFFFFu, cv, o);
    if (lane == 0) s_rc[wid] = cv;
    __syncthreads();

    if (tid == 0) {
        float c = 0.0f;
        #pragma unroll
        for (int i = 0; i < APB / 32; i++) c += s_rc[i];
        g_clsp[t] = c;
        __threadfence();
        const unsigned tk = atomicAdd(&g_ticket, 1u);
        s_last = (tk == (unsigned)(NBLK - 1));
    }
    __syncthreads();

    // Last sweep CTA: reduce everything, write output, reset flags+ticket.
    if (s_last) {
        __shared__ double f_c[B][APB / 32];
        __shared__ double f_r[B][APB / 32];
        __shared__ int    f_p[B][APB / 32];

        #pragma unroll
        for (int img = 0; img < B; img++) {
            double c = 0.0, r = 0.0;
            int p = 0;
            for (int i = tid; i < NTILES; i += APB) {
                const int idx = img * NTILES + i;
                c += (double)g_clsp[idx] + (double)g_corr[idx];
                r += (double)g_regp[idx];
                p += g_posp[idx];
            }
            #pragma unroll
            for (int o = 16; o > 0; o >>= 1) {
                c += __shfl_down_sync(0xFFFFFFFFu, c, o);
                r += __shfl_down_sync(0xFFFFFFFFu, r, o);
                p += __shfl_down_sync(0xFFFFFFFFu, p, o);
            }
            if (lane == 0) { f_c[img][wid] = c; f_r[img][wid] = r; f_p[img][wid] = p; }
        }
        __syncthreads();
        for (int i = tid; i < NBLK; i += APB) g_flag[i] = 0u;  // replay reset
        if (tid == 0) {
            double cl = 0.0, rl = 0.0;
            #pragma unroll
            for (int img = 0; img < B; img++) {
                double c = 0.0, r = 0.0;
                int p = 0;
                #pragma unroll
                for (int i = 0; i < APB / 32; i++) {
                    c += f_c[img][i]; r += f_r[img][i]; p += f_p[img][i];
                }
                const double d = (p < 1) ? 1.0 : (double)p;
                cl += c / d;
                if (p > 0) rl += r / (4.0 * d);
            }
            out[0] = (float)(cl / (double)B);
            out[1] = (float)(rl / (double)B);
            g_ticket = 0;
        }
    }
}

extern "C" void kernel_launch(void* const* d_in, const int* in_sizes, int n_in,
                              void* d_out, int out_size) {
    const float* cls = nullptr;
    const float* reg = nullptr;
    const float* anc = nullptr;
    const float* ann = nullptr;
    for (int i = 0; i < n_in; i++) {
        switch (in_sizes[i]) {
            case B * A * C:  cls = (const float*)d_in[i]; break;  // 64,000,000
            case B * A * 4:  reg = (const float*)d_in[i]; break;  //  3,200,000
            case A * 4:      anc = (const float*)d_in[i]; break;  //    400,000
            case B * M * 6:  ann = (const float*)d_in[i]; break;  //      1,536
            default: break;
        }
    }
    float* out = (float*)d_out;

    cudaFuncSetAttribute(fl_ws2_kernel,
                         cudaFuncAttributeMaxDynamicSharedMemorySize, SMEM_DYN);
    fl_ws2_kernel<<<GRID, APB, SMEM_DYN>>>(cls, reg, anc, ann, out);
}